// round 2
// baseline (speedup 1.0000x reference)
#include <cuda_runtime.h>
#include <math.h>
#include <stdint.h>

// Problem constants (fixed shapes from setup_inputs)
#define BB 8
#define CC 5
#define HH 768
#define WW 768
#define HW (HH*WW)
#define NPIX (BB*HW)          // 4,718,592  (< 2^23, fits packed root ids)
#define NTC 4

#define EPSF 1e-7f
#define ONEMF ((float)(1.0 - 1e-7))

// strips for local CCL
#define SH 8
#define SPIX (SH*WW)              // 6144
#define STRIPS_PER_IMG (HH/SH)    // 96
#define NSTRIP (BB*STRIPS_PER_IMG)// 768
#define NEDGE (BB*(STRIPS_PER_IMG-1)*WW)  // 583,680

// ---------------- static device scratch ----------------
__device__ unsigned char g_pm[NPIX];          // argmax class per pixel
__device__ int           g_label[NPIX];       // global UF (only border roots touched)
__device__ int           g_btop[NSTRIP*WW];   // packed root of top-row pixels (-1 = bg)
__device__ int           g_bbot[NSTRIP*WW];   // packed root of bottom-row pixels
__device__ double        g_acc[4][20];        // [stat][cell]: 0=cnt 1=spho 2=slog 3=sl1p
__device__ int           g_lroots[4];         // local component counts per class 1..4
__device__ int           g_merged[4];         // successful cross-strip unions per class

// ---------------- K0: zero accumulators ----------------
__global__ void k_zero() {
    int t = threadIdx.x;
    if (t < 80) ((double*)g_acc)[t] = 0.0;
    if (t < 4) { g_lroots[t] = 0; g_merged[t] = 0; }
}

// ---------------- K1: argmax + joint stats (per-lane slabs, no atomics) ----------------
// grid (96, 8), block 128. Each block: 1536 vec4 of one image.
__global__ void __launch_bounds__(128) k_stats(const float* __restrict__ pred,
                                               const int*   __restrict__ tmask) {
    __shared__ float slab[4][4][20][32];   // [warp][stat][cell][lane] — bank-conflict free
    const int tid  = threadIdx.x;
    const int warp = tid >> 5, lane = tid & 31;
    for (int k = tid; k < 4*4*20*32; k += 128) ((float*)slab)[k] = 0.f;
    __syncthreads();

    const int img = blockIdx.y;
    const float* pb = pred + (size_t)img * CC * HW;
    const int4*  tb = (const int4*)(tmask + (size_t)img * HW);
    uchar4* pmb = (uchar4*)g_pm + (size_t)img * (HW/4);
    float* my = &slab[warp][0][0][lane];
    const int start = blockIdx.x * 1536;

    #pragma unroll 2
    for (int it = 0; it < 12; ++it) {
        int v = start + it * 128 + tid;       // vec4 index within image
        int j = v * 4;
        float4 c0 = *(const float4*)(pb + j);
        float4 c1 = *(const float4*)(pb + HW + j);
        float4 c2 = *(const float4*)(pb + 2*HW + j);
        float4 c3 = *(const float4*)(pb + 3*HW + j);
        float4 c4 = *(const float4*)(pb + 4*HW + j);
        int4  tv  = tb[v];

        float A0[4] = {c0.x, c0.y, c0.z, c0.w};
        float A1[4] = {c1.x, c1.y, c1.z, c1.w};
        float A2[4] = {c2.x, c2.y, c2.z, c2.w};
        float A3[4] = {c3.x, c3.y, c3.z, c3.w};
        float A4[4] = {c4.x, c4.y, c4.z, c4.w};
        int tvv[4] = {tv.x, tv.y, tv.z, tv.w};
        unsigned char bcs[4];

        #pragma unroll
        for (int e = 0; e < 4; e++) {
            float best = A0[e]; int bc = 0;
            if (A1[e] > best) { best = A1[e]; bc = 1; }
            if (A2[e] > best) { best = A2[e]; bc = 2; }
            if (A3[e] > best) { best = A3[e]; bc = 3; }
            if (A4[e] > best) { best = A4[e]; bc = 4; }
            bcs[e] = (unsigned char)bc;

            int t = tvv[e]; t = t < 0 ? 0 : (t > 3 ? 3 : t);
            int cell = t * 5 + bc;
            float q  = bc ? best : 0.0f;
            float qc = fminf(fmaxf(q, EPSF), ONEMF);
            float lg = __logf(qc);
            float l1 = __logf(1.0f - qc);
            float* p = my + cell * 32;        // stat stride = 20*32 = 640 floats
            p[0]    += 1.0f;
            p[640]  += q;
            p[1280] += lg;
            p[1920] += l1;
        }
        pmb[v] = make_uchar4(bcs[0], bcs[1], bcs[2], bcs[3]);
    }
    __syncthreads();

    if (tid < 80) {
        int s = tid / 20, c = tid % 20;
        double acc = 0.0;
        #pragma unroll
        for (int w = 0; w < 4; w++)
            for (int l = 0; l < 32; l++) acc += (double)slab[w][s][c][l];
        atomicAdd(&g_acc[s][c], acc);
    }
}

// ---------------- shared-memory union-find ----------------
__device__ __forceinline__ int find_s(int* lab, int x) {
    int r = x, l = lab[r];
    while (l != r) { r = l; l = lab[r]; }
    int c = x;
    while (c != r) { int n = lab[c]; if (n == r) break; lab[c] = r; c = n; }
    return r;
}
__device__ __forceinline__ void union_s(int* lab, int a, int b) {
    while (true) {
        a = find_s(lab, a); b = find_s(lab, b);
        if (a == b) return;
        if (a < b) { int t = a; a = b; b = t; }
        int old = atomicCAS(&lab[a], a, b);
        if (old == a) return;
        a = old;
    }
}

// ---------------- K2: per-strip local CCL + root counts + border export ----------------
__global__ void __launch_bounds__(256) k_ccl() {
    __shared__ int lab[SPIX];
    __shared__ unsigned char pm[SPIX];
    __shared__ int rc[4];
    const int tid = threadIdx.x;
    const int strip = blockIdx.x;
    const int base = strip * SPIX;           // strips tile images exactly (HW % SPIX == 0)

    for (int v = tid; v < SPIX/16; v += 256)
        ((int4*)pm)[v] = ((const int4*)(g_pm + base))[v];
    for (int j = tid; j < SPIX; j += 256) lab[j] = j;
    if (tid < 4) rc[tid] = 0;
    __syncthreads();

    for (int j = tid; j < SPIX; j += 256) {
        int c = pm[j];
        if (!c) continue;
        int w = j - (j / WW) * WW;
        if (w       && pm[j - 1]  == c) union_s(lab, j, j - 1);
        if (j >= WW && pm[j - WW] == c) union_s(lab, j, j - WW);
    }
    __syncthreads();

    for (int j = tid; j < SPIX; j += 256) {
        int c = pm[j];
        if (c && lab[j] == j) atomicAdd(&rc[c - 1], 1);
    }
    // export borders (top row, bottom row): packed gid | class<<23, -1 for bg
    for (int w = tid; w < WW; w += 256) {
        int c = pm[w]; int val = -1;
        if (c) { int gid = base + find_s(lab, w); g_label[gid] = gid; val = gid | (c << 23); }
        g_btop[strip * WW + w] = val;
        int j = SPIX - WW + w;
        c = pm[j]; val = -1;
        if (c) { int gid = base + find_s(lab, j); g_label[gid] = gid; val = gid | (c << 23); }
        g_bbot[strip * WW + w] = val;
    }
    __syncthreads();
    if (tid < 4) atomicAdd(&g_lroots[tid], rc[tid]);
}

// ---------------- global union-find with success counting ----------------
__device__ __forceinline__ int uf_find_g(int x) {
    int r = x, l = g_label[r];
    while (l != r) { r = l; l = g_label[r]; }
    int c = x;
    while (c != r) { int n = g_label[c]; if (n == r) break; g_label[c] = r; c = n; }
    return r;
}
__device__ __forceinline__ void uf_union_g(int a, int b, int cidx) {
    while (true) {
        a = uf_find_g(a); b = uf_find_g(b);
        if (a == b) return;
        if (a < b) { int t = a; a = b; b = t; }
        int old = atomicCAS(&g_label[a], a, b);
        if (old == a) { atomicAdd(&g_merged[cidx], 1); return; }
        a = old;
    }
}

// ---------------- K3: cross-strip border merge ----------------
__global__ void k_border() {
    int e = blockIdx.x * blockDim.x + threadIdx.x;
    if (e >= NEDGE) return;
    const int per = (STRIPS_PER_IMG - 1) * WW;
    int img = e / per, r = e - img * per;
    int b = r / WW, w = r - b * WW;
    int s = img * STRIPS_PER_IMG + b;
    int va = g_bbot[s * WW + w];
    int vb = g_btop[(s + 1) * WW + w];
    if ((va | vb) < 0) return;
    int ca = va >> 23;
    if (ca != (vb >> 23)) return;
    uf_union_g(va & 0x7FFFFF, vb & 0x7FFFFF, ca - 1);
}

// ---------------- K4: scalar assembly ----------------
__global__ void k_final(float* __restrict__ out) {
    if (threadIdx.x != 0 || blockIdx.x != 0) return;

    long long cnt[4][5];
    double spho[4][5], slog[4][5], slog1p[4][5];
    for (int t = 0; t < 4; t++)
        for (int c = 0; c < 5; c++) {
            int k = t * 5 + c;
            cnt[t][c]    = (long long)(g_acc[0][k] + 0.5);
            spho[t][c]   = g_acc[1][k];
            slog[t][c]   = g_acc[2][k];
            slog1p[t][c] = g_acc[3][k];
        }
    long long cpm[5] = {0,0,0,0,0};
    long long ctm[4] = {0,0,0,0};
    for (int t = 0; t < 4; t++)
        for (int c = 0; c < 5; c++) { cpm[c] += cnt[t][c]; ctm[t] += cnt[t][c]; }

    // exact-f32 emulation of ph class values
    float phv[5] = {0.f,0.f,0.f,0.f,0.f};
    int last_i = 1;
    for (int v = 1; v < 5; v++) {
        bool present = (cpm[v] > 0);
        int has_bg = (cpm[v] < (long long)NPIX) ? 1 : 0;
        int nc = g_lroots[v - 1] - g_merged[v - 1];
        int wrapped = (int)((unsigned int)nc * (unsigned int)last_i);
        float s = (float)wrapped;
        if (present) {
            #pragma unroll
            for (int c = 0; c < 5; c++) {
                float ind = (c == v) ? 1.0f : 0.0f;
                float inc = ind + s;
                phv[c] = phv[c] + inc;
            }
            last_i += nc + has_bg;
        }
    }

    const double Nd = (double)NPIX;
    const double dEPS  = (double)EPSF;
    const double dONEM = (double)ONEMF;
    const double LOG_EPS     = log(dEPS);
    const double LOG_ONEM    = log(dONEM);
    const double LOG1P_NEPS  = log1p(-dEPS);
    const double LOG1P_NONEM = log1p(-dONEM);

    double res = 0.0;

    { // term 0: bce_dice(pm==0, tm==0)
        long long n00 = cnt[0][0];
        long long np0 = cpm[0];
        long long nt0 = ctm[0];
        double bsum = (double)n00 * LOG_ONEM
                    + (double)(nt0 - n00) * LOG_EPS
                    + (double)(np0 - n00) * LOG1P_NONEM
                    + (double)((long long)NPIX - nt0 - np0 + n00) * LOG1P_NEPS;
        double bce = -bsum / Nd;
        double dice = 1.0 - (2.0 * (double)n00 + 1.0) / ((double)np0 + (double)nt0 + 1.0);
        res += bce + dice;
    }

    for (int t = 1; t < NTC; t++) {
        long long nt = ctm[t];
        if (nt <= 0) continue;

        int ord[5] = {0,1,2,3,4};
        for (int i = 1; i < 5; i++) {
            int o = ord[i]; float v = phv[o]; int j = i - 1;
            while (j >= 0 && phv[ord[j]] > v) { ord[j+1] = ord[j]; j--; }
            ord[j+1] = o;
        }
        long long kk = (nt - 1) / 2;
        float med = phv[ord[4]];
        long long cum = 0;
        for (int j = 0; j < 5; j++) {
            cum += cnt[t][ord[j]];
            if (cum > kk) { med = phv[ord[j]]; break; }
        }
        bool sel[5];
        #pragma unroll
        for (int c = 0; c < 5; c++) sel[c] = (phv[c] == med);

        double bsum = 0.0, sum_p = 0.0, inter = 0.0, extra_sum = 0.0;
        for (int c = 0; c < 5; c++) {
            if (sel[c]) {
                bsum += slog[t][c];
                inter += spho[t][c];
                for (int tt = 0; tt < 4; tt++) {
                    sum_p += spho[tt][c];
                    if (tt != t) bsum += slog1p[tt][c];
                }
            } else {
                bsum += (double)cnt[t][c] * LOG_EPS;
                extra_sum += spho[t][c];
                for (int tt = 0; tt < 4; tt++)
                    if (tt != t) bsum += (double)cnt[tt][c] * LOG1P_NEPS;
            }
        }
        double bce = -bsum / Nd;
        double dice = 1.0 - (2.0 * inter + 1.0) / (sum_p + (double)nt + 1.0);
        double extra = extra_sum / (double)(nt > 0 ? nt : 1);
        res += bce + dice + extra;
    }

    int nu = 0;
    for (int t = 0; t < NTC; t++) if (ctm[t] > 0) nu++;
    out[0] = (float)(res / (double)(2 * nu + 1));
}

// ---------------- launch ----------------
extern "C" void kernel_launch(void* const* d_in, const int* in_sizes, int n_in,
                              void* d_out, int out_size) {
    const float* pred = (const float*)d_in[0];
    const int*   tm   = (const int*)d_in[1];
    float* out = (float*)d_out;
    (void)in_sizes; (void)n_in; (void)out_size;

    k_zero<<<1, 96>>>();
    k_stats<<<dim3(96, 8), 128>>>(pred, tm);
    k_ccl<<<NSTRIP, 256>>>();
    k_border<<<(NEDGE + 255) / 256, 256>>>();
    k_final<<<1, 1>>>(out);
}